// round 1
// baseline (speedup 1.0000x reference)
#include <cuda_runtime.h>
#include <cuda_bf16.h>

// ---------------- problem constants ----------------
#define BB    2
#define SS    2048
#define DD    1024
#define NHQ   16
#define NKVH  4
#define HDH   64
#define EE    8
#define HIDM  1365
#define CAPE  1280
#define TT    4096   // B*S tokens

// ---------------- scratch (device globals; no cudaMalloc allowed) ----------------
__device__ float g_xn [TT * DD];
__device__ float g_q  [TT * DD];
__device__ float g_k  [TT * NKVH * HDH];
__device__ float g_ao [TT * DD];
__device__ float g_h  [TT * DD];
__device__ float g_hn [TT * DD];
__device__ float g_h1s[TT * HIDM];
__device__ float g_h3s[TT * HIDM];
__device__ float g_eh1[EE * CAPE * HIDM];
__device__ float g_eh3[EE * CAPE * HIDM];
__device__ float g_probs[TT * EE];
__device__ int   g_ridx[TT * 2];
__device__ float g_rwt [TT * 2];
__device__ int   g_ecnt[EE];
__device__ int   g_eidx[EE * CAPE];
__device__ float g_ew  [EE * CAPE];

// ---------------- rmsnorm ----------------
__global__ __launch_bounds__(256) void rmsnorm_kernel(
    const float* __restrict__ x, const float* __restrict__ w, float* __restrict__ y)
{
    long t = blockIdx.x;
    const float* xr = x + t * DD;
    float ss = 0.f;
    for (int d = threadIdx.x; d < DD; d += 256) { float v = xr[d]; ss += v * v; }
    for (int off = 16; off; off >>= 1) ss += __shfl_xor_sync(0xffffffffu, ss, off);
    __shared__ float red[8];
    __shared__ float rfac;
    if ((threadIdx.x & 31) == 0) red[threadIdx.x >> 5] = ss;
    __syncthreads();
    if (threadIdx.x == 0) {
        float s2 = 0.f;
        #pragma unroll
        for (int i = 0; i < 8; i++) s2 += red[i];
        rfac = rsqrtf(s2 / (float)DD + 1e-6f);
    }
    __syncthreads();
    float r = rfac;
    float* yr = y + t * DD;
    for (int d = threadIdx.x; d < DD; d += 256) yr[d] = xr[d] * r * w[d];
}

// ---------------- generic SGEMM: C[M,N] = A[M,K] @ B[K,N] ----------------
// aidx    : optional gather of A rows (A row i = A + aidx[i]*K)
// Mcnt    : optional device row count (effective M = *Mcnt, grid sized for max M)
// residual: optional C = acc + residual
// cidx/rowscale: scatter epilogue  atomicAdd(C[cidx[r]*N+c], rowscale[r]*acc)
__global__ __launch_bounds__(256) void sgemm_kernel(
    const float* __restrict__ A, const float* __restrict__ B, float* __restrict__ C,
    int M, int N, int K,
    const int* __restrict__ aidx, const int* __restrict__ Mcnt,
    const float* __restrict__ residual,
    const int* __restrict__ cidx, const float* __restrict__ rowscale)
{
    __shared__ float As[16 * 68];
    __shared__ float Bs[16 * 68];
    const int Meff = Mcnt ? *Mcnt : M;
    const int row0 = blockIdx.y * 64;
    const int col0 = blockIdx.x * 64;
    if (row0 >= Meff) return;
    const int tid = threadIdx.x;
    const int tx = tid & 15, ty = tid >> 4;
    const int am = tid >> 2;            // A load: row within tile
    const int ak = (tid & 3) * 4;       // A load: k within tile
    const int bk = tid >> 4;            // B load: k within tile
    const int bn = (tid & 15) * 4;      // B load: col within tile

    long abase = -1;
    {
        int gr = row0 + am;
        if (gr < Meff) {
            int ar = aidx ? aidx[gr] : gr;
            abase = (long)ar * K;
        }
    }

    float acc[4][4] = {};
    for (int k0 = 0; k0 < K; k0 += 16) {
        #pragma unroll
        for (int j = 0; j < 4; j++) {
            int kk = k0 + ak + j;
            float v = 0.f;
            if (abase >= 0 && kk < K) v = A[abase + kk];
            As[(ak + j) * 68 + am] = v;
        }
        {
            int kk = k0 + bk;
            const float* brow = B + (long)kk * N;
            #pragma unroll
            for (int j = 0; j < 4; j++) {
                int cc = col0 + bn + j;
                float v = 0.f;
                if (kk < K && cc < N) v = brow[cc];
                Bs[bk * 68 + bn + j] = v;
            }
        }
        __syncthreads();
        #pragma unroll
        for (int kk = 0; kk < 16; kk++) {
            float4 av = *(const float4*)&As[kk * 68 + ty * 4];
            float4 bv = *(const float4*)&Bs[kk * 68 + tx * 4];
            acc[0][0] += av.x * bv.x; acc[0][1] += av.x * bv.y; acc[0][2] += av.x * bv.z; acc[0][3] += av.x * bv.w;
            acc[1][0] += av.y * bv.x; acc[1][1] += av.y * bv.y; acc[1][2] += av.y * bv.z; acc[1][3] += av.y * bv.w;
            acc[2][0] += av.z * bv.x; acc[2][1] += av.z * bv.y; acc[2][2] += av.z * bv.z; acc[2][3] += av.z * bv.w;
            acc[3][0] += av.w * bv.x; acc[3][1] += av.w * bv.y; acc[3][2] += av.w * bv.z; acc[3][3] += av.w * bv.w;
        }
        __syncthreads();
    }

    #pragma unroll
    for (int i = 0; i < 4; i++) {
        int r = row0 + ty * 4 + i;
        if (r >= Meff) continue;
        #pragma unroll
        for (int j = 0; j < 4; j++) {
            int c = col0 + tx * 4 + j;
            if (c >= N) continue;
            float v = acc[i][j];
            if (cidx) {
                atomicAdd(&C[(long)cidx[r] * N + c], rowscale[r] * v);
            } else {
                if (residual) v += residual[(long)r * N + c];
                C[(long)r * N + c] = v;
            }
        }
    }
}

// ---------------- RoPE (half-split) ----------------
__global__ void rope_kernel(const float* __restrict__ in, float* __restrict__ outp,
                            const float* __restrict__ cs, const float* __restrict__ sn,
                            int H, int total)
{
    for (int idx = blockIdx.x * blockDim.x + threadIdx.x; idx < total;
         idx += gridDim.x * blockDim.x) {
        int d = idx & 31;
        int h = (idx >> 5) % H;
        int t = idx / (32 * H);
        int s = t & (SS - 1);
        long base = ((long)t * H + h) * HDH + d;
        float x1 = in[base], x2 = in[base + 32];
        float c = cs[s * HDH + d], si = sn[s * HDH + d];
        outp[base]      = x1 * c - x2 * si;
        outp[base + 32] = x1 * si + x2 * c;
    }
}

// ---------------- flash attention (64x64 tiles, HD=64, causal) ----------------
__global__ __launch_bounds__(256) void flash_attn_kernel(
    const float* __restrict__ Q, const float* __restrict__ Kg,
    const float* __restrict__ Vg, float* __restrict__ O)
{
    const int b = blockIdx.z, h = blockIdx.y, qt = blockIdx.x;
    const int hk = h >> 2;          // NREP = 4
    const int s0 = qt * 64;
    extern __shared__ float sm[];
    float* Qst = sm;                // [d][r], stride 68 (transposed)
    float* Kst = sm + 64 * 68;      // [d][c], stride 68 (transposed)
    float* Vs  = sm + 2 * 64 * 68;  // [r][d]
    float* Ps  = sm + 3 * 64 * 68;  // [r][c]
    const int tid = threadIdx.x, tx = tid & 15, ty = tid >> 4;

    for (int i = tid; i < 64 * 64; i += 256) {
        int r = i >> 6, d = i & 63;
        Qst[d * 68 + r] = Q[(((long)b * SS + s0 + r) * NHQ + h) * HDH + d];
    }
    float m_i[4], l_i[4], o[4][4];
    #pragma unroll
    for (int i = 0; i < 4; i++) {
        m_i[i] = -1e30f; l_i[i] = 0.f;
        #pragma unroll
        for (int j = 0; j < 4; j++) o[i][j] = 0.f;
    }
    __syncthreads();

    for (int kt = 0; kt <= qt; kt++) {
        for (int i = tid; i < 64 * 64; i += 256) {
            int r = i >> 6, d = i & 63;
            long base = (((long)b * SS + kt * 64 + r) * NKVH + hk) * HDH + d;
            Kst[d * 68 + r] = Kg[base];
            Vs [r * 68 + d] = Vg[base];
        }
        __syncthreads();

        float s[4][4] = {};
        #pragma unroll 4
        for (int d = 0; d < 64; d++) {
            float4 av = *(const float4*)&Qst[d * 68 + ty * 4];
            float4 bv = *(const float4*)&Kst[d * 68 + tx * 4];
            s[0][0] += av.x * bv.x; s[0][1] += av.x * bv.y; s[0][2] += av.x * bv.z; s[0][3] += av.x * bv.w;
            s[1][0] += av.y * bv.x; s[1][1] += av.y * bv.y; s[1][2] += av.y * bv.z; s[1][3] += av.y * bv.w;
            s[2][0] += av.z * bv.x; s[2][1] += av.z * bv.y; s[2][2] += av.z * bv.z; s[2][3] += av.z * bv.w;
            s[3][0] += av.w * bv.x; s[3][1] += av.w * bv.y; s[3][2] += av.w * bv.z; s[3][3] += av.w * bv.w;
        }
        bool diag = (kt == qt);
        #pragma unroll
        for (int i = 0; i < 4; i++) {
            #pragma unroll
            for (int j = 0; j < 4; j++) {
                s[i][j] *= 0.125f;
                if (diag && (tx * 4 + j) > (ty * 4 + i)) s[i][j] = -1e30f;
            }
        }
        float mnew[4], alpha[4];
        #pragma unroll
        for (int i = 0; i < 4; i++) {
            float rm = fmaxf(fmaxf(s[i][0], s[i][1]), fmaxf(s[i][2], s[i][3]));
            for (int off = 8; off; off >>= 1) rm = fmaxf(rm, __shfl_xor_sync(0xffffffffu, rm, off));
            mnew[i] = fmaxf(m_i[i], rm);
            alpha[i] = __expf(m_i[i] - mnew[i]);
        }
        #pragma unroll
        for (int i = 0; i < 4; i++) {
            float sum = 0.f;
            #pragma unroll
            for (int j = 0; j < 4; j++) { s[i][j] = __expf(s[i][j] - mnew[i]); sum += s[i][j]; }
            for (int off = 8; off; off >>= 1) sum += __shfl_xor_sync(0xffffffffu, sum, off);
            l_i[i] = l_i[i] * alpha[i] + sum;
            m_i[i] = mnew[i];
            #pragma unroll
            for (int j = 0; j < 4; j++) o[i][j] *= alpha[i];
        }
        #pragma unroll
        for (int i = 0; i < 4; i++)
            #pragma unroll
            for (int j = 0; j < 4; j++)
                Ps[(ty * 4 + i) * 68 + tx * 4 + j] = s[i][j];
        __syncthreads();
        #pragma unroll 4
        for (int kk = 0; kk < 64; kk++) {
            float4 vv = *(const float4*)&Vs[kk * 68 + tx * 4];
            float p0 = Ps[(ty * 4 + 0) * 68 + kk];
            float p1 = Ps[(ty * 4 + 1) * 68 + kk];
            float p2 = Ps[(ty * 4 + 2) * 68 + kk];
            float p3 = Ps[(ty * 4 + 3) * 68 + kk];
            o[0][0] += p0 * vv.x; o[0][1] += p0 * vv.y; o[0][2] += p0 * vv.z; o[0][3] += p0 * vv.w;
            o[1][0] += p1 * vv.x; o[1][1] += p1 * vv.y; o[1][2] += p1 * vv.z; o[1][3] += p1 * vv.w;
            o[2][0] += p2 * vv.x; o[2][1] += p2 * vv.y; o[2][2] += p2 * vv.z; o[2][3] += p2 * vv.w;
            o[3][0] += p3 * vv.x; o[3][1] += p3 * vv.y; o[3][2] += p3 * vv.z; o[3][3] += p3 * vv.w;
        }
        __syncthreads();
    }

    #pragma unroll
    for (int i = 0; i < 4; i++) {
        float inv = 1.f / l_i[i];
        long base = (((long)b * SS + s0 + ty * 4 + i) * NHQ + h) * HDH + tx * 4;
        #pragma unroll
        for (int j = 0; j < 4; j++) O[base + j] = o[i][j] * inv;
    }
}

// ---------------- router: logits -> softmax -> top2 ----------------
__global__ __launch_bounds__(128) void router_kernel(
    const float* __restrict__ hn, const float* __restrict__ rw,
    float* __restrict__ probs, int* __restrict__ ridx, float* __restrict__ rwt)
{
    int t = blockIdx.x;
    __shared__ float sl[EE];
    if (threadIdx.x < EE) sl[threadIdx.x] = 0.f;
    __syncthreads();
    const float* xr = hn + (long)t * DD;
    float part[EE] = {};
    for (int d = threadIdx.x; d < DD; d += 128) {
        float xv = xr[d];
        #pragma unroll
        for (int e = 0; e < EE; e++) part[e] += xv * rw[d * EE + e];
    }
    #pragma unroll
    for (int e = 0; e < EE; e++)
        for (int off = 16; off; off >>= 1) part[e] += __shfl_xor_sync(0xffffffffu, part[e], off);
    if ((threadIdx.x & 31) == 0)
        #pragma unroll
        for (int e = 0; e < EE; e++) atomicAdd(&sl[e], part[e]);
    __syncthreads();
    if (threadIdx.x == 0) {
        float mx = sl[0];
        #pragma unroll
        for (int e = 1; e < EE; e++) mx = fmaxf(mx, sl[e]);
        float p[EE], se = 0.f;
        #pragma unroll
        for (int e = 0; e < EE; e++) { p[e] = __expf(sl[e] - mx); se += p[e]; }
        #pragma unroll
        for (int e = 0; e < EE; e++) { p[e] /= se; probs[t * EE + e] = p[e]; }
        int i0 = 0;
        #pragma unroll
        for (int e = 1; e < EE; e++) if (p[e] > p[i0]) i0 = e;
        int i1 = (i0 == 0) ? 1 : 0;
        #pragma unroll
        for (int e = 0; e < EE; e++) if (e != i0 && p[e] > p[i1]) i1 = e;
        float w0 = p[i0], w1 = p[i1], swv = w0 + w1;
        ridx[2 * t] = i0; ridx[2 * t + 1] = i1;
        rwt[2 * t] = w0 / swv; rwt[2 * t + 1] = w1 / swv;
    }
}

// ---------------- routing build: counts/capacity/gate lists + aux/util ----------------
__global__ __launch_bounds__(256) void route_build_kernel(
    const float* __restrict__ probs, const int* __restrict__ ridx,
    const float* __restrict__ rwt, float* __restrict__ aux_out, float* __restrict__ util_out,
    int* __restrict__ ecnt, int* __restrict__ eidx, float* __restrict__ ew)
{
    __shared__ float psum[EE];
    __shared__ int counts[EE];
    if (threadIdx.x < EE) psum[threadIdx.x] = 0.f;
    __syncthreads();
    float part[EE] = {};
    for (int t = threadIdx.x; t < TT; t += 256)
        #pragma unroll
        for (int e = 0; e < EE; e++) part[e] += probs[t * EE + e];
    #pragma unroll
    for (int e = 0; e < EE; e++)
        for (int off = 16; off; off >>= 1) part[e] += __shfl_xor_sync(0xffffffffu, part[e], off);
    if ((threadIdx.x & 31) == 0)
        #pragma unroll
        for (int e = 0; e < EE; e++) atomicAdd(&psum[e], part[e]);
    __syncthreads();
    if (threadIdx.x < EE) {
        int e = threadIdx.x;
        int cnt = 0, kept = 0;
        for (int t = 0; t < TT; t++) {
            int i0 = ridx[2 * t], i1 = ridx[2 * t + 1];
            if (i0 == e || i1 == e) {
                cnt++;
                if (cnt <= CAPE) {
                    eidx[e * CAPE + kept] = t;
                    ew[e * CAPE + kept] = (i0 == e) ? rwt[2 * t] : rwt[2 * t + 1];
                    kept++;
                }
            }
        }
        counts[e] = cnt;
        ecnt[e] = kept;
    }
    __syncthreads();
    if (threadIdx.x == 0) {
        float aux = 0.f, util = 0.f;
        #pragma unroll
        for (int e = 0; e < EE; e++) {
            aux += (psum[e] / (float)TT) * ((float)counts[e] / (float)TT);
            if (counts[e] > 0) util += 1.f;
        }
        *aux_out = (float)EE * aux;
        *util_out = util / (float)EE * 100.f;
    }
}

// ---------------- silu(h1)*h3 -> h1 ----------------
__global__ void silumul_kernel(float* __restrict__ h1, const float* __restrict__ h3,
                               int maxrows, int ncols, const int* __restrict__ cnt)
{
    int rows = cnt ? *cnt : maxrows;
    int total = rows * ncols;
    for (int i = blockIdx.x * blockDim.x + threadIdx.x; i < total;
         i += gridDim.x * blockDim.x) {
        float a = h1[i], b = h3[i];
        h1[i] = (a / (1.f + __expf(-a))) * b;
    }
}

// ---------------- host launcher ----------------
static inline void gemm(const float* A, const float* B, float* C, int M, int N, int K,
                        const int* aidx = nullptr, const int* Mcnt = nullptr,
                        const float* res = nullptr, const int* cidx = nullptr,
                        const float* rs = nullptr)
{
    dim3 grid((N + 63) / 64, (M + 63) / 64);
    sgemm_kernel<<<grid, 256>>>(A, B, C, M, N, K, aidx, Mcnt, res, cidx, rs);
}

extern "C" void kernel_launch(void* const* d_in, const int* in_sizes, int n_in,
                              void* d_out, int out_size)
{
    const float* x      = (const float*)d_in[0];
    const float* cosp   = (const float*)d_in[1];
    const float* sinp   = (const float*)d_in[2];
    /* mask d_in[3] unused: causal mask applied analytically */
    const float* attn_w = (const float*)d_in[4];
    const float* moe_w  = (const float*)d_in[5];
    const float* wq     = (const float*)d_in[6];
    const float* wk     = (const float*)d_in[7];
    const float* wv     = (const float*)d_in[8];
    const float* wo     = (const float*)d_in[9];
    const float* rw     = (const float*)d_in[10];
    const float* ew1    = (const float*)d_in[11];
    const float* ew2    = (const float*)d_in[12];
    const float* ew3    = (const float*)d_in[13];
    const float* sw1    = (const float*)d_in[14];
    const float* sw2    = (const float*)d_in[15];
    const float* sw3    = (const float*)d_in[16];

    float* out  = (float*)d_out;                       // [B,S,D]
    float* aux  = out + (long)TT * DD;                 // scalar
    float* util = aux + 1;                             // scalar
    float* nk   = util + 1;                            // [B,S,NKV,HD]
    float* nv   = nk + (long)TT * NKVH * HDH;          // [B,S,NKV,HD]

    float *p_xn, *p_q, *p_k, *p_ao, *p_h, *p_hn, *p_h1s, *p_h3s, *p_eh1, *p_eh3, *p_probs, *p_rwt, *p_ew;
    int *p_ridx, *p_ecnt, *p_eidx;
    cudaGetSymbolAddress((void**)&p_xn, g_xn);
    cudaGetSymbolAddress((void**)&p_q, g_q);
    cudaGetSymbolAddress((void**)&p_k, g_k);
    cudaGetSymbolAddress((void**)&p_ao, g_ao);
    cudaGetSymbolAddress((void**)&p_h, g_h);
    cudaGetSymbolAddress((void**)&p_hn, g_hn);
    cudaGetSymbolAddress((void**)&p_h1s, g_h1s);
    cudaGetSymbolAddress((void**)&p_h3s, g_h3s);
    cudaGetSymbolAddress((void**)&p_eh1, g_eh1);
    cudaGetSymbolAddress((void**)&p_eh3, g_eh3);
    cudaGetSymbolAddress((void**)&p_probs, g_probs);
    cudaGetSymbolAddress((void**)&p_ridx, g_ridx);
    cudaGetSymbolAddress((void**)&p_rwt, g_rwt);
    cudaGetSymbolAddress((void**)&p_ecnt, g_ecnt);
    cudaGetSymbolAddress((void**)&p_eidx, g_eidx);
    cudaGetSymbolAddress((void**)&p_ew, g_ew);

    // 1. attn rmsnorm
    rmsnorm_kernel<<<TT, 256>>>(x, attn_w, p_xn);
    // 2. QKV projections (V goes straight to new_v output: RoPE doesn't touch V)
    gemm(p_xn, wq, p_q, TT, NHQ * HDH, DD);
    gemm(p_xn, wk, p_k, TT, NKVH * HDH, DD);
    gemm(p_xn, wv, nv,  TT, NKVH * HDH, DD);
    // 3. RoPE: q in-place, k -> new_k output
    rope_kernel<<<2048, 256>>>(p_q, p_q, cosp, sinp, NHQ, TT * NHQ * 32);
    rope_kernel<<<512, 256>>>(p_k, nk, cosp, sinp, NKVH, TT * NKVH * 32);
    // 4. flash attention (reads K/V from the output buffers)
    cudaFuncSetAttribute(flash_attn_kernel, cudaFuncAttributeMaxDynamicSharedMemorySize, 4 * 64 * 68 * 4);
    flash_attn_kernel<<<dim3(SS / 64, NHQ, BB), 256, 4 * 64 * 68 * 4>>>(p_q, nk, nv, p_ao);
    // 5. output projection + residual
    gemm(p_ao, wo, p_h, TT, DD, NHQ * HDH, nullptr, nullptr, x);
    // 6. moe rmsnorm
    rmsnorm_kernel<<<TT, 256>>>(p_h, moe_w, p_hn);
    // 7. router + routing build (aux/util written here)
    router_kernel<<<TT, 128>>>(p_hn, rw, p_probs, p_ridx, p_rwt);
    route_build_kernel<<<1, 256>>>(p_probs, p_ridx, p_rwt, aux, util, p_ecnt, p_eidx, p_ew);
    // 8. shared expert: out = h + swiglu(hn)
    gemm(p_hn, sw1, p_h1s, TT, HIDM, DD);
    gemm(p_hn, sw3, p_h3s, TT, HIDM, DD);
    silumul_kernel<<<2048, 256>>>(p_h1s, p_h3s, TT, HIDM, nullptr);
    gemm(p_h1s, sw2, out, TT, DD, HIDM, nullptr, nullptr, p_h);
    // 9. routed experts: gather -> swiglu -> scatter-add (capacity-bounded)
    for (int e = 0; e < EE; e++) {
        const float* w1e = ew1 + (long)e * DD * HIDM;
        const float* w3e = ew3 + (long)e * DD * HIDM;
        const float* w2e = ew2 + (long)e * HIDM * DD;
        float* h1e = p_eh1 + (long)e * CAPE * HIDM;
        float* h3e = p_eh3 + (long)e * CAPE * HIDM;
        const int* idxe = p_eidx + e * CAPE;
        gemm(p_hn, w1e, h1e, CAPE, HIDM, DD, idxe, p_ecnt + e);
        gemm(p_hn, w3e, h3e, CAPE, HIDM, DD, idxe, p_ecnt + e);
        silumul_kernel<<<512, 256>>>(h1e, h3e, CAPE, HIDM, p_ecnt + e);
        gemm(h1e, w2e, out, CAPE, DD, HIDM, nullptr, p_ecnt + e, nullptr, idxe, p_ew + e * CAPE);
    }
}